// round 3
// baseline (speedup 1.0000x reference)
#include <cuda_runtime.h>
#include <math.h>

#define BATCH  64
#define NPATCH 196
#define NROWS  (BATCH * NPATCH)   // 12544
#define TDIM   1024
#define PDIM   768

// ---------------- scratch (static device allocations; no cudaMalloc) --------
__device__ float g_patches[NROWS * PDIM];            // 38.5 MB
__device__ float g_x [NROWS * TDIM];                 // 51.4 MB
__device__ float g_xn[NROWS * TDIM];
__device__ float g_q [NROWS * TDIM];
__device__ float g_k [NROWS * TDIM];
__device__ float g_G [NROWS * TDIM];
__device__ float g_A [BATCH * NPATCH * NPATCH];      // 9.8 MB
__device__ float g_mean[BATCH * TDIM];

// ---------------- reductions ------------------------------------------------
__device__ __forceinline__ float warp_sum(float v) {
#pragma unroll
    for (int o = 16; o; o >>= 1) v += __shfl_xor_sync(0xffffffffu, v, o);
    return v;
}
__device__ __forceinline__ float warp_max(float v) {
#pragma unroll
    for (int o = 16; o; o >>= 1) v = fmaxf(v, __shfl_xor_sync(0xffffffffu, v, o));
    return v;
}
// two simultaneous block sums over 256 threads (8 warps). sm must hold 16 floats.
__device__ __forceinline__ void block_sum2(float& a, float& b, float* sm) {
    a = warp_sum(a);
    b = warp_sum(b);
    int w = threadIdx.x >> 5, l = threadIdx.x & 31;
    if (l == 0) { sm[w] = a; sm[8 + w] = b; }
    __syncthreads();
    float ta = 0.f, tb = 0.f;
#pragma unroll
    for (int i = 0; i < 8; i++) { ta += sm[i]; tb += sm[8 + i]; }
    a = ta; b = tb;
}

// ---------------- patchify + LayerNorm(768) ---------------------------------
// row = b*196 + n ; feature f = p1*48 + p2*3 + c ; value = image[b,c,hp*16+p1,wp*16+p2]
__global__ void patchify_ln_kernel(const float* __restrict__ img,
                                   const float* __restrict__ gam,
                                   const float* __restrict__ bet) {
    __shared__ float sv[PDIM];
    __shared__ float sred[16];
    int row = blockIdx.x;
    int b = row / NPATCH, n = row % NPATCH;
    int hp = n / 14, wp = n % 14;
    const float* base = img + (size_t)b * 3 * 224 * 224;
    int tid = threadIdx.x;
    float s = 0.f, s2 = 0.f;
#pragma unroll
    for (int i = 0; i < 3; i++) {
        int f = tid + i * 256;
        int p1 = f / 48, r = f % 48, p2 = r / 3, c = r % 3;
        float v = base[((size_t)c * 224 + hp * 16 + p1) * 224 + wp * 16 + p2];
        sv[f] = v; s += v; s2 += v * v;
    }
    block_sum2(s, s2, sred);
    float m = s * (1.f / 768.f);
    float rstd = rsqrtf(s2 * (1.f / 768.f) - m * m + 1e-5f);
    float* out = g_patches + (size_t)row * PDIM;
#pragma unroll
    for (int i = 0; i < 3; i++) {
        int f = tid + i * 256;
        out[f] = (sv[f] - m) * rstd * gam[f] + bet[f];
    }
}

// ---------------- LayerNorm(1024), optional +pos -----------------------------
__global__ void ln1024_kernel(const float* __restrict__ in, float* __restrict__ out,
                              const float* __restrict__ gam, const float* __restrict__ bet,
                              const float* __restrict__ pos) {
    __shared__ float sred[16];
    int row = blockIdx.x, tid = threadIdx.x;   // 256 threads, float4 each
    const float4* ip = (const float4*)(in + (size_t)row * TDIM);
    float4 v = ip[tid];
    float s  = v.x + v.y + v.z + v.w;
    float s2 = v.x * v.x + v.y * v.y + v.z * v.z + v.w * v.w;
    block_sum2(s, s2, sred);
    float m = s * (1.f / 1024.f);
    float rstd = rsqrtf(s2 * (1.f / 1024.f) - m * m + 1e-5f);
    float4 gg = ((const float4*)gam)[tid];
    float4 bb = ((const float4*)bet)[tid];
    float4 o;
    o.x = (v.x - m) * rstd * gg.x + bb.x;
    o.y = (v.y - m) * rstd * gg.y + bb.y;
    o.z = (v.z - m) * rstd * gg.z + bb.z;
    o.w = (v.w - m) * rstd * gg.w + bb.w;
    if (pos) {
        int n = row % NPATCH;
        float4 p = ((const float4*)(pos + (size_t)n * TDIM))[tid];
        o.x += p.x; o.y += p.y; o.z += p.z; o.w += p.w;
    }
    ((float4*)(out + (size_t)row * TDIM))[tid] = o;
}

// ---------------- row softmax over 196 ---------------------------------------
__global__ void softmax196_kernel(float* __restrict__ S) {
    __shared__ float sred[16];
    int row = blockIdx.x, tid = threadIdx.x;   // 256 threads
    float* p = S + (size_t)row * NPATCH;
    float v = (tid < NPATCH) ? p[tid] : -1e30f;
    float mx = warp_max(v);
    int w = tid >> 5, l = tid & 31;
    if (l == 0) sred[w] = mx;
    __syncthreads();
    float bm = -1e30f;
#pragma unroll
    for (int i = 0; i < 8; i++) bm = fmaxf(bm, sred[i]);
    float e = (tid < NPATCH) ? expf(v - bm) : 0.f;
    __syncthreads();                     // sred reuse
    float s = warp_sum(e);
    if (l == 0) sred[w] = s;
    __syncthreads();
    float bs = 0.f;
#pragma unroll
    for (int i = 0; i < 8; i++) bs += sred[i];
    if (tid < NPATCH) p[tid] = e / bs;
}

// ---------------- mean over tokens -------------------------------------------
__global__ void mean_kernel() {
    int b = blockIdx.x, tid = threadIdx.x;   // 256 threads, float4 each
    const float4* xp = (const float4*)(g_x + (size_t)b * NPATCH * TDIM);
    float4 acc = make_float4(0.f, 0.f, 0.f, 0.f);
    for (int n = 0; n < NPATCH; n++) {
        float4 v = xp[(size_t)n * 256 + tid];
        acc.x += v.x; acc.y += v.y; acc.z += v.z; acc.w += v.w;
    }
    const float inv = 1.f / 196.f;
    float4 o = make_float4(acc.x * inv, acc.y * inv, acc.z * inv, acc.w * inv);
    ((float4*)(g_mean + (size_t)b * TDIM))[tid] = o;
}

// ---------------- generic batched SGEMM --------------------------------------
// C = alpha * A(MxK) @ op(B) + bias + resid
// TB=false: B is KxN row-major. TB=true: B is NxK row-major (C = A @ B^T).
// 64x64 tile, BK=16, 256 threads, 4x4 microtile.
template <bool TB>
__global__ void __launch_bounds__(256) gemm_kernel(
    const float* __restrict__ A, const float* __restrict__ B, float* __restrict__ C,
    int M, int N, int K,
    long long sA, long long sB, long long sC,
    float alpha, const float* __restrict__ bias,
    const float* __restrict__ resid, long long sR)
{
    __shared__ float As[16][64];
    __shared__ float Bs[16][64];
    const int bz = blockIdx.z;
    A += (size_t)bz * sA;
    B += (size_t)bz * sB;
    C += (size_t)bz * sC;
    if (resid) resid += (size_t)bz * sR;

    const int tid = threadIdx.x;
    const int tx = tid & 15, ty = tid >> 4;
    const int row0 = blockIdx.y * 64;
    const int col0 = blockIdx.x * 64;

    float acc[4][4];
#pragma unroll
    for (int i = 0; i < 4; i++)
#pragma unroll
        for (int j = 0; j < 4; j++) acc[i][j] = 0.f;

    const int lrow   = tid >> 2;        // 0..63
    const int lk4    = (tid & 3) * 4;   // 0,4,8,12
    const int brow16 = tid >> 4;        // 0..15
    const int bcol4  = (tid & 15) * 4;  // 0..60

    for (int k0 = 0; k0 < K; k0 += 16) {
        // ---- A tile (transposed into smem) ----
        float4 av = make_float4(0.f, 0.f, 0.f, 0.f);
        {
            int r = row0 + lrow;
            int kc = k0 + lk4;
            if (r < M) {
                if (kc + 3 < K) {
                    av = *(const float4*)(A + (size_t)r * K + kc);
                } else {
                    float t0 = (kc + 0 < K) ? A[(size_t)r * K + kc + 0] : 0.f;
                    float t1 = (kc + 1 < K) ? A[(size_t)r * K + kc + 1] : 0.f;
                    float t2 = (kc + 2 < K) ? A[(size_t)r * K + kc + 2] : 0.f;
                    float t3 = (kc + 3 < K) ? A[(size_t)r * K + kc + 3] : 0.f;
                    av = make_float4(t0, t1, t2, t3);
                }
            }
        }
        As[lk4 + 0][lrow] = av.x; As[lk4 + 1][lrow] = av.y;
        As[lk4 + 2][lrow] = av.z; As[lk4 + 3][lrow] = av.w;

        // ---- B tile ----
        if (!TB) {
            float4 bv = make_float4(0.f, 0.f, 0.f, 0.f);
            int kc = k0 + brow16;
            int cc = col0 + bcol4;
            if (kc < K && cc < N) {
                if (cc + 3 < N) {
                    bv = *(const float4*)(B + (size_t)kc * N + cc);
                } else {
                    float t0 = B[(size_t)kc * N + cc];
                    float t1 = (cc + 1 < N) ? B[(size_t)kc * N + cc + 1] : 0.f;
                    float t2 = (cc + 2 < N) ? B[(size_t)kc * N + cc + 2] : 0.f;
                    float t3 = (cc + 3 < N) ? B[(size_t)kc * N + cc + 3] : 0.f;
                    bv = make_float4(t0, t1, t2, t3);
                }
            }
            *(float4*)&Bs[brow16][bcol4] = bv;
        } else {
            float4 bv = make_float4(0.f, 0.f, 0.f, 0.f);
            int nn = col0 + lrow;
            int kc = k0 + lk4;
            if (nn < N) {
                if (kc + 3 < K) {
                    bv = *(const float4*)(B + (size_t)nn * K + kc);
                } else {
                    float t0 = (kc + 0 < K) ? B[(size_t)nn * K + kc + 0] : 0.f;
                    float t1 = (kc + 1 < K) ? B[(size_t)nn * K + kc + 1] : 0.f;
                    float t2 = (kc + 2 < K) ? B[(size_t)nn * K + kc + 2] : 0.f;
                    float t3 = (kc + 3 < K) ? B[(size_t)nn * K + kc + 3] : 0.f;
                    bv = make_float4(t0, t1, t2, t3);
                }
            }
            Bs[lk4 + 0][lrow] = bv.x; Bs[lk4 + 1][lrow] = bv.y;
            Bs[lk4 + 2][lrow] = bv.z; Bs[lk4 + 3][lrow] = bv.w;
        }
        __syncthreads();

#pragma unroll
        for (int kk = 0; kk < 16; kk++) {
            float4 a = *(const float4*)&As[kk][ty * 4];
            float4 b = *(const float4*)&Bs[kk][tx * 4];
            acc[0][0] = fmaf(a.x, b.x, acc[0][0]);
            acc[0][1] = fmaf(a.x, b.y, acc[0][1]);
            acc[0][2] = fmaf(a.x, b.z, acc[0][2]);
            acc[0][3] = fmaf(a.x, b.w, acc[0][3]);
            acc[1][0] = fmaf(a.y, b.x, acc[1][0]);
            acc[1][1] = fmaf(a.y, b.y, acc[1][1]);
            acc[1][2] = fmaf(a.y, b.z, acc[1][2]);
            acc[1][3] = fmaf(a.y, b.w, acc[1][3]);
            acc[2][0] = fmaf(a.z, b.x, acc[2][0]);
            acc[2][1] = fmaf(a.z, b.y, acc[2][1]);
            acc[2][2] = fmaf(a.z, b.z, acc[2][2]);
            acc[2][3] = fmaf(a.z, b.w, acc[2][3]);
            acc[3][0] = fmaf(a.w, b.x, acc[3][0]);
            acc[3][1] = fmaf(a.w, b.y, acc[3][1]);
            acc[3][2] = fmaf(a.w, b.z, acc[3][2]);
            acc[3][3] = fmaf(a.w, b.w, acc[3][3]);
        }
        __syncthreads();
    }

    // ---- epilogue ----
#pragma unroll
    for (int i = 0; i < 4; i++) {
        int r = row0 + ty * 4 + i;
        if (r >= M) continue;
#pragma unroll
        for (int j = 0; j < 4; j++) {
            int c = col0 + tx * 4 + j;
            if (c >= N) continue;
            float v = alpha * acc[i][j];
            if (bias)  v += bias[c];
            if (resid) v += resid[(size_t)r * N + c];
            C[(size_t)r * N + c] = v;
        }
    }
}

// ---------------- launch -----------------------------------------------------
extern "C" void kernel_launch(void* const* d_in, const int* in_sizes, int n_in,
                              void* d_out, int out_size)
{
    const float* image  = (const float*)d_in[0];
    const float* ln1_g  = (const float*)d_in[1];
    const float* ln1_b  = (const float*)d_in[2];
    const float* W_emb  = (const float*)d_in[3];
    const float* b_emb  = (const float*)d_in[4];
    const float* ln2_g  = (const float*)d_in[5];
    const float* ln2_b  = (const float*)d_in[6];
    const float* pos    = (const float*)d_in[7];
    const float* norm_g = (const float*)d_in[8];
    const float* norm_b = (const float*)d_in[9];
    const float* WV     = (const float*)d_in[10];
    const float* WK     = (const float*)d_in[11];
    const float* WQ     = (const float*)d_in[12];
    const float* lastW  = (const float*)d_in[13];
    const float* lastb  = (const float*)d_in[14];
    float* out = (float*)d_out;

    float *px, *pxn, *pq, *pk, *pG, *pA, *pPatch, *pMean;
    cudaGetSymbolAddress((void**)&px,     g_x);
    cudaGetSymbolAddress((void**)&pxn,    g_xn);
    cudaGetSymbolAddress((void**)&pq,     g_q);
    cudaGetSymbolAddress((void**)&pk,     g_k);
    cudaGetSymbolAddress((void**)&pG,     g_G);
    cudaGetSymbolAddress((void**)&pA,     g_A);
    cudaGetSymbolAddress((void**)&pPatch, g_patches);
    cudaGetSymbolAddress((void**)&pMean,  g_mean);

    const long long sQK = (long long)NPATCH * TDIM;     // 196*1024
    const long long sAA = (long long)NPATCH * NPATCH;   // 196*196
    const float scale = 0.08838834764831845f;           // 128^-0.5

    // patchify + LN1
    patchify_ln_kernel<<<NROWS, 256>>>(image, ln1_g, ln1_b);
    // embed: patches(12544x768) @ W_emb(768x1024) + b_emb  -> g_q (temp)
    gemm_kernel<false><<<dim3(16, 196, 1), 256>>>(pPatch, W_emb, pq,
        NROWS, TDIM, PDIM, 0, 0, 0, 1.f, b_emb, nullptr, 0);
    // LN2 + pos -> x
    ln1024_kernel<<<NROWS, 256>>>(pq, px, ln2_g, ln2_b, pos);

    for (int l = 0; l < 6; l++) {
        // xn = LN(x)
        ln1024_kernel<<<NROWS, 256>>>(px, pxn, norm_g, norm_b, nullptr);
        // q = xn @ WQ ; k = xn @ WK  (12544 x 1024 x 1024)
        gemm_kernel<false><<<dim3(16, 196, 1), 256>>>(pxn, WQ, pq,
            NROWS, TDIM, TDIM, 0, 0, 0, 1.f, nullptr, nullptr, 0);
        gemm_kernel<false><<<dim3(16, 196, 1), 256>>>(pxn, WK, pk,
            NROWS, TDIM, TDIM, 0, 0, 0, 1.f, nullptr, nullptr, 0);
        // G: per-head xn @ WV == (12544*8 x 128) @ (128 x 128)
        gemm_kernel<false><<<dim3(2, 1568, 1), 256>>>(pxn, WV, pG,
            NROWS * 8, 128, 128, 0, 0, 0, 1.f, nullptr, nullptr, 0);
        // S = scale * q @ k^T   (batched over 64, 196x196x1024)
        gemm_kernel<true><<<dim3(4, 4, BATCH), 256>>>(pq, pk, pA,
            NPATCH, NPATCH, TDIM, sQK, sQK, sAA, scale, nullptr, nullptr, 0);
        // A = softmax(S) rows
        softmax196_kernel<<<BATCH * NPATCH, 256>>>(pA);
        // x = A @ G + xn  (batched, 196x1024x196)
        gemm_kernel<false><<<dim3(16, 4, BATCH), 256>>>(pA, pG, px,
            NPATCH, TDIM, NPATCH, sAA, sQK, sQK, 1.f, nullptr, pxn, sQK);
    }

    // mean over tokens, then classifier
    mean_kernel<<<BATCH, 256>>>();
    gemm_kernel<false><<<dim3(16, 1, 1), 256>>>(pMean, lastW, out,
        BATCH, 1000, TDIM, 0, 0, 0, 1.f, lastb, nullptr, 0);
}

// round 4
// speedup vs baseline: 3.2080x; 3.2080x over previous
#include <cuda_runtime.h>
#include <math.h>

#define BATCH  64
#define NPATCH 196
#define NROWS  (BATCH * NPATCH)   // 12544
#define TDIM   1024
#define PDIM   768

// ---------------- scratch (static device allocations; no cudaMalloc) --------
__device__ float g_patches[NROWS * PDIM];
__device__ float g_x [NROWS * TDIM];
__device__ float g_xn[NROWS * TDIM];
__device__ float g_q [NROWS * TDIM];
__device__ float g_k [NROWS * TDIM];
__device__ float g_kt[BATCH * TDIM * NPATCH];
__device__ float g_G [NROWS * TDIM];
__device__ float g_A [BATCH * NPATCH * NPATCH];
__device__ float g_mean[BATCH * TDIM];

// ---------------- reductions ------------------------------------------------
__device__ __forceinline__ float warp_sum(float v) {
#pragma unroll
    for (int o = 16; o; o >>= 1) v += __shfl_xor_sync(0xffffffffu, v, o);
    return v;
}
__device__ __forceinline__ float warp_max(float v) {
#pragma unroll
    for (int o = 16; o; o >>= 1) v = fmaxf(v, __shfl_xor_sync(0xffffffffu, v, o));
    return v;
}
__device__ __forceinline__ void block_sum2(float& a, float& b, float* sm) {
    a = warp_sum(a);
    b = warp_sum(b);
    int w = threadIdx.x >> 5, l = threadIdx.x & 31;
    if (l == 0) { sm[w] = a; sm[8 + w] = b; }
    __syncthreads();
    float ta = 0.f, tb = 0.f;
#pragma unroll
    for (int i = 0; i < 8; i++) { ta += sm[i]; tb += sm[8 + i]; }
    a = ta; b = tb;
}

// ---------------- patchify + LayerNorm(768) ---------------------------------
__global__ void patchify_ln_kernel(const float* __restrict__ img,
                                   const float* __restrict__ gam,
                                   const float* __restrict__ bet) {
    __shared__ float sv[PDIM];
    __shared__ float sred[16];
    int row = blockIdx.x;
    int b = row / NPATCH, n = row % NPATCH;
    int hp = n / 14, wp = n % 14;
    const float* base = img + (size_t)b * 3 * 224 * 224;
    int tid = threadIdx.x;
    float s = 0.f, s2 = 0.f;
#pragma unroll
    for (int i = 0; i < 3; i++) {
        int f = tid + i * 256;
        int p1 = f / 48, r = f % 48, p2 = r / 3, c = r % 3;
        float v = base[((size_t)c * 224 + hp * 16 + p1) * 224 + wp * 16 + p2];
        sv[f] = v; s += v; s2 += v * v;
    }
    block_sum2(s, s2, sred);
    float m = s * (1.f / 768.f);
    float rstd = rsqrtf(s2 * (1.f / 768.f) - m * m + 1e-5f);
    float* out = g_patches + (size_t)row * PDIM;
#pragma unroll
    for (int i = 0; i < 3; i++) {
        int f = tid + i * 256;
        out[f] = (sv[f] - m) * rstd * gam[f] + bet[f];
    }
}

// ---------------- LayerNorm(1024), optional +pos -----------------------------
__global__ void ln1024_kernel(const float* __restrict__ in, float* __restrict__ out,
                              const float* __restrict__ gam, const float* __restrict__ bet,
                              const float* __restrict__ pos) {
    __shared__ float sred[16];
    int row = blockIdx.x, tid = threadIdx.x;
    const float4* ip = (const float4*)(in + (size_t)row * TDIM);
    float4 v = ip[tid];
    float s  = v.x + v.y + v.z + v.w;
    float s2 = v.x * v.x + v.y * v.y + v.z * v.z + v.w * v.w;
    block_sum2(s, s2, sred);
    float m = s * (1.f / 1024.f);
    float rstd = rsqrtf(s2 * (1.f / 1024.f) - m * m + 1e-5f);
    float4 gg = ((const float4*)gam)[tid];
    float4 bb = ((const float4*)bet)[tid];
    float4 o;
    o.x = (v.x - m) * rstd * gg.x + bb.x;
    o.y = (v.y - m) * rstd * gg.y + bb.y;
    o.z = (v.z - m) * rstd * gg.z + bb.z;
    o.w = (v.w - m) * rstd * gg.w + bb.w;
    if (pos) {
        int n = row % NPATCH;
        float4 p = ((const float4*)(pos + (size_t)n * TDIM))[tid];
        o.x += p.x; o.y += p.y; o.z += p.z; o.w += p.w;
    }
    ((float4*)(out + (size_t)row * TDIM))[tid] = o;
}

// ---------------- row softmax over 196 ---------------------------------------
__global__ void softmax196_kernel(float* __restrict__ S) {
    __shared__ float sred[16];
    int row = blockIdx.x, tid = threadIdx.x;
    float* p = S + (size_t)row * NPATCH;
    float v = (tid < NPATCH) ? p[tid] : -1e30f;
    float mx = warp_max(v);
    int w = tid >> 5, l = tid & 31;
    if (l == 0) sred[w] = mx;
    __syncthreads();
    float bm = -1e30f;
#pragma unroll
    for (int i = 0; i < 8; i++) bm = fmaxf(bm, sred[i]);
    float e = (tid < NPATCH) ? expf(v - bm) : 0.f;
    __syncthreads();
    float s = warp_sum(e);
    if (l == 0) sred[w] = s;
    __syncthreads();
    float bs = 0.f;
#pragma unroll
    for (int i = 0; i < 8; i++) bs += sred[i];
    if (tid < NPATCH) p[tid] = e / bs;
}

// ---------------- mean over tokens -------------------------------------------
__global__ void mean_kernel() {
    int b = blockIdx.x, tid = threadIdx.x;
    const float4* xp = (const float4*)(g_x + (size_t)b * NPATCH * TDIM);
    float4 acc = make_float4(0.f, 0.f, 0.f, 0.f);
    for (int n = 0; n < NPATCH; n++) {
        float4 v = xp[(size_t)n * 256 + tid];
        acc.x += v.x; acc.y += v.y; acc.z += v.z; acc.w += v.w;
    }
    const float inv = 1.f / 196.f;
    float4 o = make_float4(acc.x * inv, acc.y * inv, acc.z * inv, acc.w * inv);
    ((float4*)(g_mean + (size_t)b * TDIM))[tid] = o;
}

// ---------------- batched transpose (196x1024 -> 1024x196) -------------------
__global__ void transpose_k_kernel(const float* __restrict__ in, float* __restrict__ out) {
    __shared__ float t[32][33];
    int b = blockIdx.z;
    const float* ip = in + (size_t)b * NPATCH * TDIM;
    float* op = out + (size_t)b * TDIM * NPATCH;
    int c0 = blockIdx.x * 32, r0 = blockIdx.y * 32;
    int x = threadIdx.x, y = threadIdx.y;     // 32 x 8
#pragma unroll
    for (int i = 0; i < 32; i += 8) {
        int r = r0 + y + i, c = c0 + x;
        t[y + i][x] = (r < NPATCH) ? ip[(size_t)r * TDIM + c] : 0.f;
    }
    __syncthreads();
#pragma unroll
    for (int i = 0; i < 32; i += 8) {
        int c = c0 + y + i, r = r0 + x;
        if (r < NPATCH) op[(size_t)c * NPATCH + r] = t[x][y + i];
    }
}

// ---------------- TF32 tensor-core GEMM --------------------------------------
// C = alpha * A(MxK, row-major) @ B(KxN, row-major) + bias + resid
// block tile 128x128x32, 256 threads = 8 warps (2x4), warp tile 64x32.
__device__ __forceinline__ unsigned f2tf32(float f) {
    unsigned u;
    asm("cvt.rna.tf32.f32 %0, %1;" : "=r"(u) : "f"(f));
    return u;
}

__global__ void __launch_bounds__(256, 2) gemm_tc(
    const float* __restrict__ A, const float* __restrict__ B, float* __restrict__ C,
    int M, int N, int K,
    long long sA, long long sB, long long sC,
    float alpha, const float* __restrict__ bias,
    const float* __restrict__ resid, long long sR)
{
    __shared__ unsigned As[128][36];   // [m][k], row stride 36 (conflict-free)
    __shared__ unsigned Bs[32][136];   // [k][n], row stride 136 (conflict-free)

    const int bz = blockIdx.z;
    A += (size_t)bz * sA;
    B += (size_t)bz * sB;
    C += (size_t)bz * sC;
    if (resid) resid += (size_t)bz * sR;

    const int tid  = threadIdx.x;
    const int lane = tid & 31, warp = tid >> 5;
    const int wm = warp >> 2, wn = warp & 3;       // 2 x 4 warp grid
    const int g = lane >> 2, t = lane & 3;

    const int row0 = blockIdx.y * 128;
    const int col0 = blockIdx.x * 128;

    float c[4][4][4];
#pragma unroll
    for (int i = 0; i < 4; i++)
#pragma unroll
        for (int j = 0; j < 4; j++)
#pragma unroll
            for (int r = 0; r < 4; r++) c[i][j][r] = 0.f;

    const int ktiles = (K + 31) / 32;
    for (int kt = 0; kt < ktiles; kt++) {
        const int k0g = kt * 32;

        // ---- load A tile 128x32 (row-major in smem) ----
#pragma unroll
        for (int it = 0; it < 4; it++) {
            int m  = (tid >> 3) + it * 32;
            int kc = (tid & 7) * 4;
            int gr = row0 + m, gk = k0g + kc;
            float4 v = make_float4(0.f, 0.f, 0.f, 0.f);
            if (gr < M && gk < K) v = *(const float4*)(A + (size_t)gr * K + gk);
            uint4 u;
            u.x = f2tf32(v.x); u.y = f2tf32(v.y);
            u.z = f2tf32(v.z); u.w = f2tf32(v.w);
            *(uint4*)&As[m][kc] = u;
        }
        // ---- load B tile 32x128 ----
#pragma unroll
        for (int it = 0; it < 4; it++) {
            int k  = (tid >> 5) + it * 8;
            int n  = (tid & 31) * 4;
            int gk = k0g + k, gn = col0 + n;
            float4 v = make_float4(0.f, 0.f, 0.f, 0.f);
            if (gk < K && gn < N) v = *(const float4*)(B + (size_t)gk * N + gn);
            uint4 u;
            u.x = f2tf32(v.x); u.y = f2tf32(v.y);
            u.z = f2tf32(v.z); u.w = f2tf32(v.w);
            *(uint4*)&Bs[k][n] = u;
        }
        __syncthreads();

#pragma unroll
        for (int kk = 0; kk < 4; kk++) {
            const int ks = kk * 8;
            unsigned a[4][4], bq[4][2];
#pragma unroll
            for (int mt = 0; mt < 4; mt++) {
                int am = wm * 64 + mt * 16 + g;
                a[mt][0] = As[am    ][ks + t];
                a[mt][1] = As[am + 8][ks + t];
                a[mt][2] = As[am    ][ks + t + 4];
                a[mt][3] = As[am + 8][ks + t + 4];
            }
#pragma unroll
            for (int nt = 0; nt < 4; nt++) {
                int bn = wn * 32 + nt * 8 + g;
                bq[nt][0] = Bs[ks + t    ][bn];
                bq[nt][1] = Bs[ks + t + 4][bn];
            }
#pragma unroll
            for (int mt = 0; mt < 4; mt++)
#pragma unroll
                for (int nt = 0; nt < 4; nt++) {
                    asm volatile(
                        "mma.sync.aligned.m16n8k8.row.col.f32.tf32.tf32.f32 "
                        "{%0,%1,%2,%3}, {%4,%5,%6,%7}, {%8,%9}, {%0,%1,%2,%3};\n"
                        : "+f"(c[mt][nt][0]), "+f"(c[mt][nt][1]),
                          "+f"(c[mt][nt][2]), "+f"(c[mt][nt][3])
                        : "r"(a[mt][0]), "r"(a[mt][1]), "r"(a[mt][2]), "r"(a[mt][3]),
                          "r"(bq[nt][0]), "r"(bq[nt][1]));
                }
        }
        __syncthreads();
    }

    // ---- epilogue ----
#pragma unroll
    for (int mt = 0; mt < 4; mt++) {
        int r = row0 + wm * 64 + mt * 16 + g;
#pragma unroll
        for (int nt = 0; nt < 4; nt++) {
            int cb = col0 + wn * 32 + nt * 8 + 2 * t;
#pragma unroll
            for (int half = 0; half < 2; half++) {
                int rr = r + half * 8;
                if (rr >= M) continue;
                float v0 = alpha * c[mt][nt][half * 2 + 0];
                float v1 = alpha * c[mt][nt][half * 2 + 1];
                if (bias) { v0 += bias[cb]; v1 += bias[cb + 1]; }
                if (resid) {
                    v0 += resid[(size_t)rr * N + cb];
                    v1 += resid[(size_t)rr * N + cb + 1];
                }
                if (cb < N)     C[(size_t)rr * N + cb]     = v0;
                if (cb + 1 < N) C[(size_t)rr * N + cb + 1] = v1;
            }
        }
    }
}

// ---------------- small SIMT GEMM (classifier only) ---------------------------
__global__ void __launch_bounds__(256) gemm_simt(
    const float* __restrict__ A, const float* __restrict__ B, float* __restrict__ C,
    int M, int N, int K, const float* __restrict__ bias)
{
    __shared__ float As[16][64];
    __shared__ float Bs[16][64];
    const int tid = threadIdx.x;
    const int tx = tid & 15, ty = tid >> 4;
    const int row0 = blockIdx.y * 64;
    const int col0 = blockIdx.x * 64;

    float acc[4][4];
#pragma unroll
    for (int i = 0; i < 4; i++)
#pragma unroll
        for (int j = 0; j < 4; j++) acc[i][j] = 0.f;

    const int lrow   = tid >> 2;
    const int lk4    = (tid & 3) * 4;
    const int brow16 = tid >> 4;
    const int bcol4  = (tid & 15) * 4;

    for (int k0 = 0; k0 < K; k0 += 16) {
        float4 av = make_float4(0.f, 0.f, 0.f, 0.f);
        {
            int r = row0 + lrow, kc = k0 + lk4;
            if (r < M && kc < K) av = *(const float4*)(A + (size_t)r * K + kc);
        }
        As[lk4 + 0][lrow] = av.x; As[lk4 + 1][lrow] = av.y;
        As[lk4 + 2][lrow] = av.z; As[lk4 + 3][lrow] = av.w;

        float4 bv = make_float4(0.f, 0.f, 0.f, 0.f);
        {
            int kc = k0 + brow16, cc = col0 + bcol4;
            if (kc < K && cc < N) {
                if (cc + 3 < N) bv = *(const float4*)(B + (size_t)kc * N + cc);
                else {
                    bv.x = B[(size_t)kc * N + cc];
                    if (cc + 1 < N) bv.y = B[(size_t)kc * N + cc + 1];
                    if (cc + 2 < N) bv.z = B[(size_t)kc * N + cc + 2];
                }
            }
        }
        *(float4*)&Bs[brow16][bcol4] = bv;
        __syncthreads();

#pragma unroll
        for (int kk = 0; kk < 16; kk++) {
            float4 a = *(const float4*)&As[kk][ty * 4];
            float4 b = *(const float4*)&Bs[kk][tx * 4];
            acc[0][0] = fmaf(a.x, b.x, acc[0][0]); acc[0][1] = fmaf(a.x, b.y, acc[0][1]);
            acc[0][2] = fmaf(a.x, b.z, acc[0][2]); acc[0][3] = fmaf(a.x, b.w, acc[0][3]);
            acc[1][0] = fmaf(a.y, b.x, acc[1][0]); acc[1][1] = fmaf(a.y, b.y, acc[1][1]);
            acc[1][2] = fmaf(a.y, b.z, acc[1][2]); acc[1][3] = fmaf(a.y, b.w, acc[1][3]);
            acc[2][0] = fmaf(a.z, b.x, acc[2][0]); acc[2][1] = fmaf(a.z, b.y, acc[2][1]);
            acc[2][2] = fmaf(a.z, b.z, acc[2][2]); acc[2][3] = fmaf(a.z, b.w, acc[2][3]);
            acc[3][0] = fmaf(a.w, b.x, acc[3][0]); acc[3][1] = fmaf(a.w, b.y, acc[3][1]);
            acc[3][2] = fmaf(a.w, b.z, acc[3][2]); acc[3][3] = fmaf(a.w, b.w, acc[3][3]);
        }
        __syncthreads();
    }

#pragma unroll
    for (int i = 0; i < 4; i++) {
        int r = row0 + ty * 4 + i;
        if (r >= M) continue;
#pragma unroll
        for (int j = 0; j < 4; j++) {
            int cc = col0 + tx * 4 + j;
            if (cc >= N) continue;
            float v = acc[i][j];
            if (bias) v += bias[cc];
            C[(size_t)r * N + cc] = v;
        }
    }
}

// ---------------- launch -----------------------------------------------------
extern "C" void kernel_launch(void* const* d_in, const int* in_sizes, int n_in,
                              void* d_out, int out_size)
{
    const float* image  = (const float*)d_in[0];
    const float* ln1_g  = (const float*)d_in[1];
    const float* ln1_b  = (const float*)d_in[2];
    const float* W_emb  = (const float*)d_in[3];
    const float* b_emb  = (const float*)d_in[4];
    const float* ln2_g  = (const float*)d_in[5];
    const float* ln2_b  = (const float*)d_in[6];
    const float* pos    = (const float*)d_in[7];
    const float* norm_g = (const float*)d_in[8];
    const float* norm_b = (const float*)d_in[9];
    const float* WV     = (const float*)d_in[10];
    const float* WK     = (const float*)d_in[11];
    const float* WQ     = (const float*)d_in[12];
    const float* lastW  = (const float*)d_in[13];
    const float* lastb  = (const float*)d_in[14];
    float* out = (float*)d_out;

    float *px, *pxn, *pq, *pk, *pkt, *pG, *pA, *pPatch, *pMean;
    cudaGetSymbolAddress((void**)&px,     g_x);
    cudaGetSymbolAddress((void**)&pxn,    g_xn);
    cudaGetSymbolAddress((void**)&pq,     g_q);
    cudaGetSymbolAddress((void**)&pk,     g_k);
    cudaGetSymbolAddress((void**)&pkt,    g_kt);
    cudaGetSymbolAddress((void**)&pG,     g_G);
    cudaGetSymbolAddress((void**)&pA,     g_A);
    cudaGetSymbolAddress((void**)&pPatch, g_patches);
    cudaGetSymbolAddress((void**)&pMean,  g_mean);

    const long long sQK = (long long)NPATCH * TDIM;
    const long long sAA = (long long)NPATCH * NPATCH;
    const long long sKT = (long long)TDIM * NPATCH;
    const float scale = 0.08838834764831845f;   // 128^-0.5

    // patchify + LN1
    patchify_ln_kernel<<<NROWS, 256>>>(image, ln1_g, ln1_b);
    // embed: patches(12544x768) @ W_emb(768x1024) + b_emb -> q (temp)
    gemm_tc<<<dim3(8, 98, 1), 256>>>(pPatch, W_emb, pq,
        NROWS, TDIM, PDIM, 0, 0, 0, 1.f, b_emb, nullptr, 0);
    // LN2 + pos -> x
    ln1024_kernel<<<NROWS, 256>>>(pq, px, ln2_g, ln2_b, pos);

    for (int l = 0; l < 6; l++) {
        ln1024_kernel<<<NROWS, 256>>>(px, pxn, norm_g, norm_b, nullptr);
        gemm_tc<<<dim3(8, 98, 1), 256>>>(pxn, WQ, pq,
            NROWS, TDIM, TDIM, 0, 0, 0, 1.f, nullptr, nullptr, 0);
        gemm_tc<<<dim3(8, 98, 1), 256>>>(pxn, WK, pk,
            NROWS, TDIM, TDIM, 0, 0, 0, 1.f, nullptr, nullptr, 0);
        transpose_k_kernel<<<dim3(32, 7, BATCH), dim3(32, 8)>>>(pk, pkt);
        // G: per-head xn @ WV == (100352 x 128) @ (128 x 128)
        gemm_tc<<<dim3(1, 784, 1), 256>>>(pxn, WV, pG,
            NROWS * 8, 128, 128, 0, 0, 0, 1.f, nullptr, nullptr, 0);
        // S = scale * q @ k^T  (via kT, batched)
        gemm_tc<<<dim3(2, 2, BATCH), 256>>>(pq, pkt, pA,
            NPATCH, NPATCH, TDIM, sQK, sKT, sAA, scale, nullptr, nullptr, 0);
        softmax196_kernel<<<BATCH * NPATCH, 256>>>(pA);
        // x = A @ G + xn
        gemm_tc<<<dim3(8, 2, BATCH), 256>>>(pA, pG, px,
            NPATCH, TDIM, NPATCH, sAA, sQK, sQK, 1.f, nullptr, pxn, sQK);
    }

    mean_kernel<<<BATCH, 256>>>();
    gemm_simt<<<dim3(16, 1, 1), 256>>>(pMean, lastW, out,
        BATCH, 1000, TDIM, lastb);
}